// round 12
// baseline (speedup 1.0000x reference)
#include <cuda_runtime.h>
#include <stdint.h>
#include <math.h>

#define S_LEN 2048
#define HID   2048
#define NH    32
#define NKV   8
#define HD    64
#define DQ    (NH * HD)    // 2048
#define DKV   (NKV * HD)   // 512
#define DQKV  (DQ + 2 * DKV)
#define NEG_HUGE (-1e30f)

// K-dim pair permutation (GEMM inputs + g_o only): store order
// [0,4,1,5,2,6,3,7] per 8-group -> mma pair (k,k+4) adjacent -> LDS.64.
// pos(j) = j<4 ? 2j : 2(j-4)+1. Each thread holds the SAME logical k
// values as unpermuted -> MMA numerics bit-identical.

// -------- scratch (no dynamic allocation allowed) --------
__device__ float g_q[S_LEN * DQ];       // 16 MB  tf32 bits, unpermuted
__device__ float g_k[S_LEN * DKV];      //  4 MB  tf32 bits, unpermuted
__device__ float g_v[S_LEN * DKV];      //  4 MB  tf32 bits, unpermuted
__device__ float g_o[S_LEN * DQ];       // 16 MB  tf32 bits, pair-permuted (O-proj A)
__device__ float g_hsT[S_LEN * HID];    // 16 MB  tf32(hs), K-permuted
__device__ float g_wqkvT[DQKV * HID];   // 24 MB  tf32(wq|wk|wv), K-permuted
__device__ float g_woT[HID * HID];      // 16 MB  tf32(wo), K-permuted

// ============================================================
// TF32 helpers
// ============================================================
__device__ __forceinline__ uint32_t f2tf32(float x) {
    uint32_t u;
    asm("cvt.rna.tf32.f32 %0, %1;" : "=r"(u) : "f"(x));
    return u;
}
__device__ __forceinline__ float tf32b(float x) {
    return __uint_as_float(f2tf32(x));
}

__device__ __forceinline__ void mma_tf32(float c[4], const uint32_t a[4], const uint32_t b[2]) {
    asm volatile(
        "mma.sync.aligned.m16n8k8.row.col.f32.tf32.tf32.f32 "
        "{%0,%1,%2,%3}, {%4,%5,%6,%7}, {%8,%9}, {%0,%1,%2,%3};"
        : "+f"(c[0]), "+f"(c[1]), "+f"(c[2]), "+f"(c[3])
        : "r"(a[0]), "r"(a[1]), "r"(a[2]), "r"(a[3]),
          "r"(b[0]), "r"(b[1]));
}

__device__ __forceinline__ void cp_async16(uint32_t smem_dst, const void* gmem_src) {
    asm volatile("cp.async.cg.shared.global [%0], [%1], 16;" :: "r"(smem_dst), "l"(gmem_src));
}

// ============================================================
// fp32 -> tf32 bits + pair-permute each 8-group.
// ============================================================
__global__ void cvt_perm(const float* __restrict__ src, float* __restrict__ dst, int n8) {
    int i = blockIdx.x * blockDim.x + threadIdx.x;
    if (i >= n8) return;
    const float4* s = reinterpret_cast<const float4*>(src) + 2 * (size_t)i;
    float4 v0 = s[0], v1 = s[1];
    float2* d = reinterpret_cast<float2*>(dst) + 4 * (size_t)i;
    d[0] = make_float2(tf32b(v0.x), tf32b(v1.x));
    d[1] = make_float2(tf32b(v0.y), tf32b(v1.y));
    d[2] = make_float2(tf32b(v0.z), tf32b(v1.z));
    d[3] = make_float2(tf32b(v0.w), tf32b(v1.w));
}

#define GK_PAD 40            // ≡8 mod 32 -> conflict-free LDS.64
#define GK_TILE (128 * GK_PAD)

// ============================================================
// Fused QKV projection + RoPE + scaling.
// Mainloop: K-permuted operands, LDS.64 fragment loads.
// Epilogue: identical to known-good R8 (unpermuted Q/K/V stores).
// ============================================================
__global__ __launch_bounds__(256) void qkv_gemm(const float* __restrict__ cosb,
                                                const float* __restrict__ sinb) {
    extern __shared__ float sm[];
    const int tid    = threadIdx.x;
    const int lane   = tid & 31;
    const int wid    = tid >> 5;
    const int warp_m = wid & 3;
    const int warp_n = wid >> 2;
    const int g      = lane >> 2;
    const int cg     = lane & 3;
    const int brow   = blockIdx.y * 128;
    const int bcol   = blockIdx.x * 128;

    const int seg = (bcol < DQ) ? 0 : ((bcol < DQ + DKV) ? 1 : 2);
    const int segbase = (seg == 0) ? 0 : ((seg == 1) ? DQ : DQ + DKV);
    const int out_col = bcol - segbase;
    const int out_ld  = (seg == 0) ? DQ : DKV;
    const float scale  = (seg == 0) ? 0.125f : 1.0f;
    float* out = (seg == 0) ? g_q : (seg == 1) ? g_k : g_v;

    float acc[2][8][4];
#pragma unroll
    for (int i = 0; i < 2; i++)
#pragma unroll
        for (int j = 0; j < 8; j++)
#pragma unroll
            for (int t = 0; t < 4; t++) acc[i][j][t] = 0.f;

    auto prefetch = [&](int stage, int k0) {
        float* As = sm + stage * (2 * GK_TILE);
        float* Bs = As + GK_TILE;
        uint32_t as_base = (uint32_t)__cvta_generic_to_shared(As);
        uint32_t bs_base = (uint32_t)__cvta_generic_to_shared(Bs);
#pragma unroll
        for (int i = 0; i < 4; i++) {
            int idx = i * 256 + tid;
            int r   = idx >> 3;
            int c4  = idx & 7;
            cp_async16(as_base + (r * GK_PAD + c4 * 4) * 4,
                       &g_hsT[(size_t)(brow + r) * HID + k0 + c4 * 4]);
            cp_async16(bs_base + (r * GK_PAD + c4 * 4) * 4,
                       &g_wqkvT[(size_t)(bcol + r) * HID + k0 + c4 * 4]);
        }
        asm volatile("cp.async.commit_group;");
    };

    int stage = 0;
    prefetch(0, 0);

    for (int k0 = 0; k0 < HID; k0 += 32) {
        const bool has_next = (k0 + 32) < HID;
        if (has_next) prefetch(stage ^ 1, k0 + 32);

        if (has_next) asm volatile("cp.async.wait_group 1;");
        else          asm volatile("cp.async.wait_group 0;");
        __syncthreads();

        const uint32_t* As = reinterpret_cast<const uint32_t*>(sm + stage * (2 * GK_TILE));
        const uint32_t* Bs = As + GK_TILE;

#pragma unroll
        for (int kk = 0; kk < 4; kk++) {
            const int kb = kk * 8;
            uint32_t Af[2][4], Bf[8][2];
#pragma unroll
            for (int mt = 0; mt < 2; mt++) {
                const uint32_t* p = &As[(warp_m * 32 + mt * 16 + g) * GK_PAD + kb + 2 * cg];
                uint2 lo = *reinterpret_cast<const uint2*>(p);
                uint2 hi = *reinterpret_cast<const uint2*>(p + 8 * GK_PAD);
                Af[mt][0] = lo.x; Af[mt][2] = lo.y;
                Af[mt][1] = hi.x; Af[mt][3] = hi.y;
            }
#pragma unroll
            for (int nt = 0; nt < 8; nt++) {
                const uint32_t* p = &Bs[(warp_n * 64 + nt * 8 + g) * GK_PAD + kb + 2 * cg];
                uint2 v = *reinterpret_cast<const uint2*>(p);
                Bf[nt][0] = v.x; Bf[nt][1] = v.y;
            }
#pragma unroll
            for (int mt = 0; mt < 2; mt++)
#pragma unroll
                for (int nt = 0; nt < 8; nt++)
                    mma_tf32(acc[mt][nt], Af[mt], Bf[nt]);
        }
        __syncthreads();
        stage ^= 1;
    }

    // ---- epilogue: RoPE in registers, store tf32 bits (R8 layout) ----
#pragma unroll
    for (int mt = 0; mt < 2; mt++) {
        const int r0 = brow + warp_m * 32 + mt * 16 + g;
        if (seg != 2) {
            const float* cb0 = cosb + r0 * HD;
            const float* sb0 = sinb + r0 * HD;
            const float* cb1 = cosb + (r0 + 8) * HD;
            const float* sb1 = sinb + (r0 + 8) * HD;
#pragma unroll
            for (int nt = 0; nt < 4; nt++) {
                const int d = nt * 8 + 2 * cg;
#pragma unroll
                for (int e = 0; e < 2; e++) {
                    const float cl0 = __ldg(cb0 + d + e);
                    const float sl0 = __ldg(sb0 + d + e);
                    const float ch0 = __ldg(cb0 + d + e + 32);
                    const float sh0 = __ldg(sb0 + d + e + 32);
                    const float cl1 = __ldg(cb1 + d + e);
                    const float sl1 = __ldg(sb1 + d + e);
                    const float ch1 = __ldg(cb1 + d + e + 32);
                    const float sh1 = __ldg(sb1 + d + e + 32);

                    const float x1 = acc[mt][nt][e],     x2 = acc[mt][nt + 4][e];
                    acc[mt][nt][e]     = (x1 * cl0 - x2 * sl0) * scale;
                    acc[mt][nt + 4][e] = (x2 * ch0 + x1 * sh0) * scale;
                    const float y1 = acc[mt][nt][e + 2], y2 = acc[mt][nt + 4][e + 2];
                    acc[mt][nt][e + 2]     = (y1 * cl1 - y2 * sl1) * scale;
                    acc[mt][nt + 4][e + 2] = (y2 * ch1 + y1 * sh1) * scale;
                }
            }
        }
        float* orow0 = out + (size_t)r0 * out_ld + out_col + warp_n * 64;
        float* orow1 = orow0 + (size_t)8 * out_ld;
#pragma unroll
        for (int nt = 0; nt < 8; nt++) {
            const int c = nt * 8 + 2 * cg;
            *reinterpret_cast<float2*>(orow0 + c) =
                make_float2(tf32b(acc[mt][nt][0]), tf32b(acc[mt][nt][1]));
            *reinterpret_cast<float2*>(orow1 + c) =
                make_float2(tf32b(acc[mt][nt][2]), tf32b(acc[mt][nt][3]));
        }
    }
}

// ============================================================
// O-projection: C = A * B^T, A(g_o)/B(woT) tf32 bits K-permuted.
// ============================================================
__global__ __launch_bounds__(256) void gemm_tf32(const float* __restrict__ A,
                                                 const float* __restrict__ B,
                                                 float* __restrict__ C,
                                                 int M, int N, int K) {
    extern __shared__ float sm[];
    const int tid    = threadIdx.x;
    const int lane   = tid & 31;
    const int wid    = tid >> 5;
    const int warp_m = wid >> 2;
    const int warp_n = wid & 3;
    const int g      = lane >> 2;
    const int cg     = lane & 3;
    const int brow   = blockIdx.y * 128;
    const int bcol   = blockIdx.x * 128;

    float acc[4][4][4];
#pragma unroll
    for (int i = 0; i < 4; i++)
#pragma unroll
        for (int j = 0; j < 4; j++)
#pragma unroll
            for (int t = 0; t < 4; t++) acc[i][j][t] = 0.f;

    auto prefetch = [&](int stage, int k0) {
        float* As = sm + stage * (2 * GK_TILE);
        float* Bs = As + GK_TILE;
        uint32_t as_base = (uint32_t)__cvta_generic_to_shared(As);
        uint32_t bs_base = (uint32_t)__cvta_generic_to_shared(Bs);
#pragma unroll
        for (int i = 0; i < 4; i++) {
            int idx = i * 256 + tid;
            int r   = idx >> 3;
            int c4  = idx & 7;
            cp_async16(as_base + (r * GK_PAD + c4 * 4) * 4,
                       &A[(size_t)(brow + r) * K + k0 + c4 * 4]);
            cp_async16(bs_base + (r * GK_PAD + c4 * 4) * 4,
                       &B[(size_t)(bcol + r) * K + k0 + c4 * 4]);
        }
        asm volatile("cp.async.commit_group;");
    };

    int stage = 0;
    prefetch(0, 0);

    for (int k0 = 0; k0 < K; k0 += 32) {
        const bool has_next = (k0 + 32) < K;
        if (has_next) prefetch(stage ^ 1, k0 + 32);

        if (has_next) asm volatile("cp.async.wait_group 1;");
        else          asm volatile("cp.async.wait_group 0;");
        __syncthreads();

        const uint32_t* As = reinterpret_cast<const uint32_t*>(sm + stage * (2 * GK_TILE));
        const uint32_t* Bs = As + GK_TILE;

#pragma unroll
        for (int kk = 0; kk < 4; kk++) {
            const int kb = kk * 8;
            uint32_t Af[4][4], Bf[4][2];
#pragma unroll
            for (int mt = 0; mt < 4; mt++) {
                const uint32_t* p = &As[(warp_m * 64 + mt * 16 + g) * GK_PAD + kb + 2 * cg];
                uint2 lo = *reinterpret_cast<const uint2*>(p);
                uint2 hi = *reinterpret_cast<const uint2*>(p + 8 * GK_PAD);
                Af[mt][0] = lo.x; Af[mt][2] = lo.y;
                Af[mt][1] = hi.x; Af[mt][3] = hi.y;
            }
#pragma unroll
            for (int nt = 0; nt < 4; nt++) {
                const uint32_t* p = &Bs[(warp_n * 32 + nt * 8 + g) * GK_PAD + kb + 2 * cg];
                uint2 v = *reinterpret_cast<const uint2*>(p);
                Bf[nt][0] = v.x; Bf[nt][1] = v.y;
            }
#pragma unroll
            for (int mt = 0; mt < 4; mt++)
#pragma unroll
                for (int nt = 0; nt < 4; nt++)
                    mma_tf32(acc[mt][nt], Af[mt], Bf[nt]);
        }
        __syncthreads();
        stage ^= 1;
    }

#pragma unroll
    for (int mt = 0; mt < 4; mt++) {
#pragma unroll
        for (int nt = 0; nt < 4; nt++) {
            int row0 = brow + warp_m * 64 + mt * 16 + g;
            int col  = bcol + warp_n * 32 + nt * 8 + 2 * cg;
            float2 v0 = make_float2(acc[mt][nt][0], acc[mt][nt][1]);
            float2 v1 = make_float2(acc[mt][nt][2], acc[mt][nt][3]);
            *reinterpret_cast<float2*>(&C[(size_t)row0 * N + col])       = v0;
            *reinterpret_cast<float2*>(&C[(size_t)(row0 + 8) * N + col]) = v1;
        }
    }
}

// ============================================================
// TF32 flash attention — byte-level R8 kernel (known good),
// except the final O store writes pair-permuted positions.
// ============================================================
#define KS_STR 68
#define VS_STR 72
#define FSTAGE (64 * KS_STR + 64 * VS_STR)

__global__ __launch_bounds__(256) void flash_tf32() {
    extern __shared__ float sm[];
    const int tid  = threadIdx.x;
    const int lane = tid & 31;
    const int w    = tid >> 5;
    const int g    = lane >> 2;
    const int cg   = lane & 3;
    const int qt   = gridDim.x - 1 - blockIdx.x;
    const int head = blockIdx.y;
    const int kvh  = head >> 2;
    const int row0 = qt * 128 + w * 16 + g;

    uint32_t qf[8][4];
    {
        const uint32_t* q0 = reinterpret_cast<const uint32_t*>(&g_q[(size_t)row0 * DQ + head * HD]);
        const uint32_t* q1 = q0 + 8 * DQ;
#pragma unroll
        for (int ks = 0; ks < 8; ks++) {
            qf[ks][0] = q0[8 * ks + cg];
            qf[ks][1] = q1[8 * ks + cg];
            qf[ks][2] = q0[8 * ks + cg + 4];
            qf[ks][3] = q1[8 * ks + cg + 4];
        }
    }

    float oacc[8][4];
#pragma unroll
    for (int nf = 0; nf < 8; nf++)
#pragma unroll
        for (int t = 0; t < 4; t++) oacc[nf][t] = 0.f;
    float m0 = NEG_HUGE, m1 = NEG_HUGE, l0 = 0.f, l1 = 0.f;

    auto prefetch = [&](int kb, int s) {
        float* Ks = sm + s * FSTAGE;
        float* Vs = Ks + 64 * KS_STR;
        uint32_t ka = (uint32_t)__cvta_generic_to_shared(Ks);
        uint32_t va = (uint32_t)__cvta_generic_to_shared(Vs);
#pragma unroll
        for (int t = 0; t < 4; t++) {
            int idx = t * 256 + tid;
            int r   = idx >> 4;
            int c4  = (idx & 15) * 4;
            cp_async16(ka + (r * KS_STR + c4) * 4,
                       &g_k[(size_t)(kb * 64 + r) * DKV + kvh * HD + c4]);
            cp_async16(va + (r * VS_STR + c4) * 4,
                       &g_v[(size_t)(kb * 64 + r) * DKV + kvh * HD + c4]);
        }
        asm volatile("cp.async.commit_group;");
    };

    const int nkb = 2 * qt + 2;
    prefetch(0, 0);

    for (int kb = 0; kb < nkb; kb++) {
        const int s = kb & 1;
        if (kb + 1 < nkb) {
            prefetch(kb + 1, s ^ 1);
            asm volatile("cp.async.wait_group 1;");
        } else {
            asm volatile("cp.async.wait_group 0;");
        }
        __syncthreads();

        const uint32_t* Ks = reinterpret_cast<const uint32_t*>(sm + s * FSTAGE);
        const uint32_t* Vs = Ks + 64 * KS_STR;

        const bool active = !(w < 4 && kb == 2 * qt + 1);
        if (active) {
            float sacc[8][4];
#pragma unroll
            for (int nf = 0; nf < 8; nf++)
#pragma unroll
                for (int t = 0; t < 4; t++) sacc[nf][t] = 0.f;

#pragma unroll
            for (int ks = 0; ks < 8; ks++) {
#pragma unroll
                for (int nf = 0; nf < 8; nf++) {
                    uint32_t b[2];
                    const uint32_t* p = &Ks[(nf * 8 + g) * KS_STR + ks * 8 + cg];
                    b[0] = p[0];
                    b[1] = p[4];
                    mma_tf32(sacc[nf], qf[ks], b);
                }
            }

            if (kb >= 2 * qt) {
#pragma unroll
                for (int nf = 0; nf < 8; nf++) {
                    int c = kb * 64 + nf * 8 + 2 * cg;
                    if (c     > row0)     sacc[nf][0] = NEG_HUGE;
                    if (c + 1 > row0)     sacc[nf][1] = NEG_HUGE;
                    if (c     > row0 + 8) sacc[nf][2] = NEG_HUGE;
                    if (c + 1 > row0 + 8) sacc[nf][3] = NEG_HUGE;
                }
            }

            float tm0 = NEG_HUGE, tm1 = NEG_HUGE;
#pragma unroll
            for (int nf = 0; nf < 8; nf++) {
                tm0 = fmaxf(tm0, fmaxf(sacc[nf][0], sacc[nf][1]));
                tm1 = fmaxf(tm1, fmaxf(sacc[nf][2], sacc[nf][3]));
            }
            tm0 = fmaxf(tm0, __shfl_xor_sync(0xffffffff, tm0, 1));
            tm0 = fmaxf(tm0, __shfl_xor_sync(0xffffffff, tm0, 2));
            tm1 = fmaxf(tm1, __shfl_xor_sync(0xffffffff, tm1, 1));
            tm1 = fmaxf(tm1, __shfl_xor_sync(0xffffffff, tm1, 2));

            const float mn0 = fmaxf(m0, tm0);
            const float mn1 = fmaxf(m1, tm1);
            const float sc0 = __expf(m0 - mn0);
            const float sc1 = __expf(m1 - mn1);

            float rs0 = 0.f, rs1 = 0.f;
#pragma unroll
            for (int nf = 0; nf < 8; nf++) {
                sacc[nf][0] = __expf(sacc[nf][0] - mn0);
                sacc[nf][1] = __expf(sacc[nf][1] - mn0);
                sacc[nf][2] = __expf(sacc[nf][2] - mn1);
                sacc[nf][3] = __expf(sacc[nf][3] - mn1);
                rs0 += sacc[nf][0] + sacc[nf][1];
                rs1 += sacc[nf][2] + sacc[nf][3];
            }
            rs0 += __shfl_xor_sync(0xffffffff, rs0, 1);
            rs0 += __shfl_xor_sync(0xffffffff, rs0, 2);
            rs1 += __shfl_xor_sync(0xffffffff, rs1, 1);
            rs1 += __shfl_xor_sync(0xffffffff, rs1, 2);

            l0 = l0 * sc0 + rs0;  m0 = mn0;
            l1 = l1 * sc1 + rs1;  m1 = mn1;
#pragma unroll
            for (int nf = 0; nf < 8; nf++) {
                oacc[nf][0] *= sc0; oacc[nf][1] *= sc0;
                oacc[nf][2] *= sc1; oacc[nf][3] *= sc1;
            }

            const int base = lane & ~3;
            const int s0l  = base + (cg >> 1);
            const int s1l  = s0l + 2;
            const bool odd = (cg & 1);
#pragma unroll
            for (int ks = 0; ks < 8; ks++) {
                const uint32_t c0 = f2tf32(sacc[ks][0]);
                const uint32_t c1 = f2tf32(sacc[ks][1]);
                const uint32_t c2 = f2tf32(sacc[ks][2]);
                const uint32_t c3 = f2tf32(sacc[ks][3]);
                uint32_t a[4];
                {
                    uint32_t t00 = __shfl_sync(0xffffffff, c0, s0l);
                    uint32_t t01 = __shfl_sync(0xffffffff, c1, s0l);
                    uint32_t t10 = __shfl_sync(0xffffffff, c0, s1l);
                    uint32_t t11 = __shfl_sync(0xffffffff, c1, s1l);
                    a[0] = odd ? t01 : t00;
                    a[2] = odd ? t11 : t10;
                    uint32_t u00 = __shfl_sync(0xffffffff, c2, s0l);
                    uint32_t u01 = __shfl_sync(0xffffffff, c3, s0l);
                    uint32_t u10 = __shfl_sync(0xffffffff, c2, s1l);
                    uint32_t u11 = __shfl_sync(0xffffffff, c3, s1l);
                    a[1] = odd ? u01 : u00;
                    a[3] = odd ? u11 : u10;
                }
#pragma unroll
                for (int nf = 0; nf < 8; nf++) {
                    uint32_t b[2];
                    const uint32_t* vp = &Vs[(ks * 8 + cg) * VS_STR + nf * 8 + g];
                    b[0] = vp[0];
                    b[1] = vp[4 * VS_STR];
                    mma_tf32(oacc[nf], a, b);
                }
            }
        }
        __syncthreads();
    }

    // normalize + store tf32 bits at pair-permuted positions (O-proj A side)
    const float inv0 = 1.f / l0;
    const float inv1 = 1.f / l1;
    const int p0 = (cg < 2) ? 4 * cg : 4 * cg - 7;       // pos(2cg)
    const int p1 = (cg < 2) ? 4 * cg + 2 : 4 * cg - 5;   // pos(2cg+1)
    float* o0 = &g_o[(size_t)row0 * DQ + head * HD];
    float* o1 = o0 + 8 * DQ;
#pragma unroll
    for (int nf = 0; nf < 8; nf++) {
        o0[nf * 8 + p0] = tf32b(oacc[nf][0] * inv0);
        o0[nf * 8 + p1] = tf32b(oacc[nf][1] * inv0);
        o1[nf * 8 + p0] = tf32b(oacc[nf][2] * inv1);
        o1[nf * 8 + p1] = tf32b(oacc[nf][3] * inv1);
    }
}

// ============================================================
extern "C" void kernel_launch(void* const* d_in, const int* in_sizes, int n_in,
                              void* d_out, int out_size) {
    const float* hs   = (const float*)d_in[0];
    const float* cosb = (const float*)d_in[1];
    const float* sinb = (const float*)d_in[2];
    // d_in[3] = attention_mask (causal) — implemented analytically
    const float* wq   = (const float*)d_in[4];
    const float* wk   = (const float*)d_in[5];
    const float* wv   = (const float*)d_in[6];
    const float* wo   = (const float*)d_in[7];
    float* out = (float*)d_out;

    float *op, *hsT, *wqkvT, *woT;
    cudaGetSymbolAddress((void**)&op,    g_o);
    cudaGetSymbolAddress((void**)&hsT,   g_hsT);
    cudaGetSymbolAddress((void**)&wqkvT, g_wqkvT);
    cudaGetSymbolAddress((void**)&woT,   g_woT);

    const int gemm_smem  = 2 * 2 * GK_TILE * (int)sizeof(float);   // 81920 B
    const int flash_smem = 2 * FSTAGE * (int)sizeof(float);        // 71680 B
    cudaFuncSetAttribute(qkv_gemm,  cudaFuncAttributeMaxDynamicSharedMemorySize, gemm_smem);
    cudaFuncSetAttribute(gemm_tf32, cudaFuncAttributeMaxDynamicSharedMemorySize, gemm_smem);
    cudaFuncSetAttribute(flash_tf32, cudaFuncAttributeMaxDynamicSharedMemorySize, flash_smem);

    // fp32 -> tf32 bits with K-dim pair permutation
    const int CB = 256;
    cvt_perm<<<(S_LEN * HID / 8 + CB - 1) / CB, CB>>>(hs, hsT, S_LEN * HID / 8);
    cvt_perm<<<(DQ * HID / 8 + CB - 1) / CB, CB>>>(wq, wqkvT, DQ * HID / 8);
    cvt_perm<<<(DKV * HID / 8 + CB - 1) / CB, CB>>>(wk, wqkvT + (size_t)DQ * HID, DKV * HID / 8);
    cvt_perm<<<(DKV * HID / 8 + CB - 1) / CB, CB>>>(wv, wqkvT + (size_t)(DQ + DKV) * HID, DKV * HID / 8);
    cvt_perm<<<(HID * HID / 8 + CB - 1) / CB, CB>>>(wo, woT, HID * HID / 8);

    // fused QKV projection + RoPE + scale
    qkv_gemm<<<dim3(DQKV / 128, S_LEN / 128), 256, gemm_smem>>>(cosb, sinb);

    // TF32 tensor-core causal flash attention (R8 kernel)
    flash_tf32<<<dim3(S_LEN / 128, NH), 256, flash_smem>>>();

    // output projection
    gemm_tf32<<<dim3(HID / 128, S_LEN / 128), 256, gemm_smem>>>(op, woT, out, S_LEN, HID, HID);
}